// round 2
// baseline (speedup 1.0000x reference)
#include <cuda_runtime.h>
#include <math.h>

#define MBATCH 512
#define EPSV 1e-5f

// ---------------- scratch (static device memory; no allocs allowed) ----------------
__device__ float g_buf1[512*24*38*38];   // conv1 out
__device__ float g_buf2[512*24*19*19];   // conv2 out
__device__ float g_buf3[512*24*10*10];   // conv3 out
__device__ float g_buf4[512*24*5*5];     // conv4 out
__device__ float g_scale[24];
__device__ float g_shift[24];
__device__ float g_U[512*25*256];
__device__ float g_V[512*25*256];
__device__ float g_HA[320000u*256];      // 327 MB ping
__device__ float g_HB[320000u*256];      // 327 MB pong
__device__ float g_XG[512*256];
__device__ float g_F1[512*256];
__device__ float g_F2[512*256];
__device__ float g_FO[512*10];

// ---------------- conv (k=3, s=2, p=1) + bias + relu ----------------
__global__ void conv_relu_kernel(const float* __restrict__ in, const float* __restrict__ w,
                                 const float* __restrict__ bias, float* __restrict__ out,
                                 int Cin, int Cout, int Hin, int Win, int Hout, int Wout,
                                 int total) {
    int idx = blockIdx.x * blockDim.x + threadIdx.x;
    if (idx >= total) return;
    int wo = idx % Wout; int t = idx / Wout;
    int ho = t % Hout;   t /= Hout;
    int co = t % Cout;   int b = t / Cout;

    float acc = bias[co];
    for (int ci = 0; ci < Cin; ci++) {
        const float* ip = in + ((size_t)(b*Cin + ci) * Hin) * Win;
        const float* wp = w + ((size_t)(co*Cin + ci) * 3) * 3;
        #pragma unroll
        for (int kh = 0; kh < 3; kh++) {
            int hi = ho*2 - 1 + kh;
            if (hi < 0 || hi >= Hin) continue;
            #pragma unroll
            for (int kw = 0; kw < 3; kw++) {
                int wi = wo*2 - 1 + kw;
                if (wi < 0 || wi >= Win) continue;
                acc += ip[hi*Win + wi] * wp[kh*3 + kw];
            }
        }
    }
    out[idx] = fmaxf(acc, 0.f);
}

// ---------------- batchnorm (training-mode batch stats) ----------------
__global__ void bn_stats_kernel(const float* __restrict__ y, const float* __restrict__ g,
                                const float* __restrict__ beta, int C, int HW,
                                float* __restrict__ scale, float* __restrict__ shift) {
    int c = blockIdx.x;
    int n = MBATCH * HW;
    float s = 0.f, s2 = 0.f;
    for (int i = threadIdx.x; i < n; i += blockDim.x) {
        int b = i / HW, p = i % HW;
        float v = y[((size_t)b*C + c) * HW + p];
        s += v; s2 += v*v;
    }
    __shared__ float sh[256], sh2[256];
    sh[threadIdx.x] = s; sh2[threadIdx.x] = s2;
    __syncthreads();
    for (int o = 128; o > 0; o >>= 1) {
        if (threadIdx.x < o) {
            sh[threadIdx.x]  += sh[threadIdx.x + o];
            sh2[threadIdx.x] += sh2[threadIdx.x + o];
        }
        __syncthreads();
    }
    if (threadIdx.x == 0) {
        float mean = sh[0] / (float)n;
        float var  = sh2[0] / (float)n - mean*mean;
        float sc = g[c] * rsqrtf(var + EPSV);
        scale[c] = sc;
        shift[c] = beta[c] - mean * sc;
    }
}

__global__ void bn_apply_kernel(float* __restrict__ y, const float* __restrict__ scale,
                                const float* __restrict__ shift, int C, int HW, int total) {
    int i = blockIdx.x * blockDim.x + threadIdx.x;
    if (i >= total) return;
    int c = (i / HW) % C;
    y[i] = y[i] * scale[c] + shift[c];
}

// ---------------- layer-1 factorization: U[b,c,k], V[b,a,k] ----------------
// gw1 [256,63]: d 0..23 = x feats (of c), 24..25 = coord(c), 26..49 = x feats (of a),
//               50..51 = coord(a), 52..62 = qst
__global__ void uv_kernel(const float* __restrict__ x4, const float* __restrict__ qst,
                          const float* __restrict__ gw1, const float* __restrict__ gb1,
                          float* __restrict__ U, float* __restrict__ V) {
    int idx = blockIdx.x * blockDim.x + threadIdx.x;   // 512*25*256
    if (idx >= 512*25*256) return;
    int k = idx & 255;
    int t = idx >> 8;
    int pos = t % 25;
    int b = t / 25;

    float cx = ((float)pos / 5.0f - 2.0f) * 0.5f;      // true division, matches i/5
    float cy = ((float)(pos % 5) - 2.0f) * 0.5f;

    const float* xr = x4 + (size_t)b*24*25 + pos;      // x4[b,ch,pos], stride 25
    const float* w  = gw1 + (size_t)k * 63;

    float u = 0.f, v = 0.f;
    #pragma unroll
    for (int ch = 0; ch < 24; ch++) {
        float xv = xr[ch*25];
        u += xv * w[ch];
        v += xv * w[26 + ch];
    }
    u += cx * w[24] + cy * w[25];
    v += cx * w[50] + cy * w[51];
    #pragma unroll
    for (int q = 0; q < 11; q++) v += qst[b*11 + q] * w[52 + q];
    v += gb1[k];

    U[idx] = u;
    V[idx] = v;
}

// h1[b,a,c,k] = relu(U[b,c,k] + V[b,a,k]); row = b*625 + a*25 + c
__global__ void h1_kernel(const float* __restrict__ U, const float* __restrict__ V,
                          float* __restrict__ H) {
    int idx = blockIdx.x * blockDim.x + threadIdx.x;   // 81,920,000
    int k = idx & 255;
    int r = idx >> 8;
    int c = r % 25; int t = r / 25;
    int a = t % 25; int b = t / 25;
    float v = U[(((size_t)b*25 + c) << 8) + k] + V[(((size_t)b*25 + a) << 8) + k];
    H[idx] = fmaxf(v, 0.f);
}

// ---------------- GEMM: C[M,N] = act(A[M,K] @ W[N,K]^T + bias) ----------------
// 64x64 block tile, BK=16, 256 threads, 4x4 per-thread micro-tile, float4 loads.
template<int RELU>
__global__ void gemm_bias_kernel(const float* __restrict__ A, const float* __restrict__ W,
                                 const float* __restrict__ bias, float* __restrict__ C,
                                 int M, int N, int K) {
    __shared__ float As[16][65];
    __shared__ float Bs[16][65];
    const int bm = blockIdx.y * 64;
    const int bn = blockIdx.x * 64;
    const int tid = threadIdx.x;
    const int tx = tid & 15;
    const int ty = tid >> 4;
    const int lrow = tid >> 2;         // 0..63
    const int lcol = (tid & 3) * 4;    // 0,4,8,12

    float acc[4][4];
    #pragma unroll
    for (int i = 0; i < 4; i++)
        #pragma unroll
        for (int j = 0; j < 4; j++) acc[i][j] = 0.f;

    for (int k0 = 0; k0 < K; k0 += 16) {
        float4 av = make_float4(0.f, 0.f, 0.f, 0.f);
        if (bm + lrow < M)
            av = *(const float4*)(A + (size_t)(bm + lrow)*K + k0 + lcol);
        As[lcol+0][lrow] = av.x; As[lcol+1][lrow] = av.y;
        As[lcol+2][lrow] = av.z; As[lcol+3][lrow] = av.w;

        float4 bv = make_float4(0.f, 0.f, 0.f, 0.f);
        if (bn + lrow < N)
            bv = *(const float4*)(W + (size_t)(bn + lrow)*K + k0 + lcol);
        Bs[lcol+0][lrow] = bv.x; Bs[lcol+1][lrow] = bv.y;
        Bs[lcol+2][lrow] = bv.z; Bs[lcol+3][lrow] = bv.w;

        __syncthreads();
        #pragma unroll
        for (int kk = 0; kk < 16; kk++) {
            float a[4], b[4];
            #pragma unroll
            for (int i = 0; i < 4; i++) a[i] = As[kk][ty*4 + i];
            #pragma unroll
            for (int j = 0; j < 4; j++) b[j] = Bs[kk][tx*4 + j];
            #pragma unroll
            for (int i = 0; i < 4; i++)
                #pragma unroll
                for (int j = 0; j < 4; j++) acc[i][j] += a[i] * b[j];
        }
        __syncthreads();
    }

    #pragma unroll
    for (int i = 0; i < 4; i++) {
        int m = bm + ty*4 + i;
        if (m >= M) continue;
        #pragma unroll
        for (int j = 0; j < 4; j++) {
            int n = bn + tx*4 + j;
            if (n >= N) continue;
            float v = acc[i][j] + bias[n];
            if (RELU) v = fmaxf(v, 0.f);
            C[(size_t)m * N + n] = v;
        }
    }
}

// ---------------- sum pooling over 625 pairs ----------------
__global__ void sumpool_kernel(const float* __restrict__ H, float* __restrict__ XG) {
    int b = blockIdx.x;
    int k = threadIdx.x;
    const float* p = H + (size_t)b * 625 * 256 + k;
    float s = 0.f;
    for (int i = 0; i < 625; i++) s += p[(size_t)i * 256];
    XG[b*256 + k] = s;
}

// ---------------- log_softmax over 10 classes ----------------
__global__ void logsoftmax_kernel(const float* __restrict__ in, float* __restrict__ out) {
    int b = blockIdx.x * blockDim.x + threadIdx.x;
    if (b >= 512) return;
    float v[10];
    float m = -1e30f;
    #pragma unroll
    for (int i = 0; i < 10; i++) { v[i] = in[b*10 + i]; m = fmaxf(m, v[i]); }
    float s = 0.f;
    #pragma unroll
    for (int i = 0; i < 10; i++) s += expf(v[i] - m);
    float ls = logf(s) + m;
    #pragma unroll
    for (int i = 0; i < 10; i++) out[b*10 + i] = v[i] - ls;
}

// ---------------- launch ----------------
extern "C" void kernel_launch(void* const* d_in, const int* in_sizes, int n_in,
                              void* d_out, int out_size) {
    const float* img  = (const float*)d_in[0];
    const float* qst  = (const float*)d_in[1];
    const float* c1w  = (const float*)d_in[2];
    const float* c1b  = (const float*)d_in[3];
    const float* bn1g = (const float*)d_in[4];
    const float* bn1b = (const float*)d_in[5];
    const float* c2w  = (const float*)d_in[6];
    const float* c2b  = (const float*)d_in[7];
    const float* bn2g = (const float*)d_in[8];
    const float* bn2b = (const float*)d_in[9];
    const float* c3w  = (const float*)d_in[10];
    const float* c3b  = (const float*)d_in[11];
    const float* bn3g = (const float*)d_in[12];
    const float* bn3b = (const float*)d_in[13];
    const float* c4w  = (const float*)d_in[14];
    const float* c4b  = (const float*)d_in[15];
    const float* bn4g = (const float*)d_in[16];
    const float* bn4b = (const float*)d_in[17];
    const float* gw1  = (const float*)d_in[18];
    const float* gb1  = (const float*)d_in[19];
    const float* gw2  = (const float*)d_in[20];
    const float* gb2  = (const float*)d_in[21];
    const float* gw3  = (const float*)d_in[22];
    const float* gb3  = (const float*)d_in[23];
    const float* gw4  = (const float*)d_in[24];
    const float* gb4  = (const float*)d_in[25];
    const float* fw1  = (const float*)d_in[26];
    const float* fb1  = (const float*)d_in[27];
    const float* fw2  = (const float*)d_in[28];
    const float* fb2  = (const float*)d_in[29];
    const float* fw3  = (const float*)d_in[30];
    const float* fb3  = (const float*)d_in[31];
    float* out = (float*)d_out;

    float *buf1, *buf2, *buf3, *buf4, *scale, *shift, *U, *V, *HA, *HB, *XG, *F1, *F2, *FO;
    cudaGetSymbolAddress((void**)&buf1, g_buf1);
    cudaGetSymbolAddress((void**)&buf2, g_buf2);
    cudaGetSymbolAddress((void**)&buf3, g_buf3);
    cudaGetSymbolAddress((void**)&buf4, g_buf4);
    cudaGetSymbolAddress((void**)&scale, g_scale);
    cudaGetSymbolAddress((void**)&shift, g_shift);
    cudaGetSymbolAddress((void**)&U, g_U);
    cudaGetSymbolAddress((void**)&V, g_V);
    cudaGetSymbolAddress((void**)&HA, g_HA);
    cudaGetSymbolAddress((void**)&HB, g_HB);
    cudaGetSymbolAddress((void**)&XG, g_XG);
    cudaGetSymbolAddress((void**)&F1, g_F1);
    cudaGetSymbolAddress((void**)&F2, g_F2);
    cudaGetSymbolAddress((void**)&FO, g_FO);

    // conv1: [512,3,75,75] -> [512,24,38,38]
    {
        int total = 512*24*38*38;
        conv_relu_kernel<<<(total+255)/256, 256>>>(img, c1w, c1b, buf1, 3, 24, 75, 75, 38, 38, total);
        bn_stats_kernel<<<24, 256>>>(buf1, bn1g, bn1b, 24, 38*38, scale, shift);
        bn_apply_kernel<<<(total+255)/256, 256>>>(buf1, scale, shift, 24, 38*38, total);
    }
    // conv2: -> [512,24,19,19]
    {
        int total = 512*24*19*19;
        conv_relu_kernel<<<(total+255)/256, 256>>>(buf1, c2w, c2b, buf2, 24, 24, 38, 38, 19, 19, total);
        bn_stats_kernel<<<24, 256>>>(buf2, bn2g, bn2b, 24, 19*19, scale, shift);
        bn_apply_kernel<<<(total+255)/256, 256>>>(buf2, scale, shift, 24, 19*19, total);
    }
    // conv3: -> [512,24,10,10]
    {
        int total = 512*24*10*10;
        conv_relu_kernel<<<(total+255)/256, 256>>>(buf2, c3w, c3b, buf3, 24, 24, 19, 19, 10, 10, total);
        bn_stats_kernel<<<24, 256>>>(buf3, bn3g, bn3b, 24, 10*10, scale, shift);
        bn_apply_kernel<<<(total+255)/256, 256>>>(buf3, scale, shift, 24, 10*10, total);
    }
    // conv4: -> [512,24,5,5]
    {
        int total = 512*24*5*5;
        conv_relu_kernel<<<(total+255)/256, 256>>>(buf3, c4w, c4b, buf4, 24, 24, 10, 10, 5, 5, total);
        bn_stats_kernel<<<24, 256>>>(buf4, bn4g, bn4b, 24, 5*5, scale, shift);
        bn_apply_kernel<<<(total+255)/256, 256>>>(buf4, scale, shift, 24, 5*5, total);
    }

    // g layer 1 factorized
    {
        int total = 512*25*256;
        uv_kernel<<<(total+255)/256, 256>>>(buf4, qst, gw1, gb1, U, V);
    }
    {
        int total = 320000 * 256;   // 81,920,000
        h1_kernel<<<total/256, 256>>>(U, V, HA);
    }

    // g layers 2-4: [320000,256] x [256,256]
    {
        dim3 grid(4, 5000), block(256);
        gemm_bias_kernel<1><<<grid, block>>>(HA, gw2, gb2, HB, 320000, 256, 256);
        gemm_bias_kernel<1><<<grid, block>>>(HB, gw3, gb3, HA, 320000, 256, 256);
        gemm_bias_kernel<1><<<grid, block>>>(HA, gw4, gb4, HB, 320000, 256, 256);
    }

    // sum pooling over 625 pairs
    sumpool_kernel<<<512, 256>>>(HB, XG);

    // f layers
    {
        dim3 grid(4, 8), block(256);
        gemm_bias_kernel<1><<<grid, block>>>(XG, fw1, fb1, F1, 512, 256, 256);
        gemm_bias_kernel<1><<<grid, block>>>(F1, fw2, fb2, F2, 512, 256, 256);
        dim3 grid3(1, 8);
        gemm_bias_kernel<0><<<grid3, block>>>(F2, fw3, fb3, FO, 512, 10, 256);
    }

    logsoftmax_kernel<<<2, 256>>>(FO, out);
}

// round 4
// speedup vs baseline: 3.1712x; 3.1712x over previous
#include <cuda_runtime.h>
#include <math.h>
#include <stdint.h>

#define EPSV 1e-5f

// ---------------- static scratch ----------------
__device__ float g_buf1[512*24*38*38];
__device__ float g_buf2[512*24*19*19];
__device__ float g_buf3[512*24*10*10];
__device__ float g_buf4[512*24*5*5];
__device__ float g_part1[24*16];
__device__ float g_part2[24*16];
__device__ float g_scale[24];
__device__ float g_shift[24];
__device__ float g_U[512*25*256];
__device__ float g_V[512*25*256];
__device__ float g_HA[320000u*256];
__device__ float g_HB[320000u*256];
__device__ float g_XG[512*256];
__device__ float g_F1[512*256];
__device__ float g_F2[512*256];
__device__ float g_FO[512*10];

// ---------------- conv: block per image, SMEM plane per ci ----------------
template<int CIN,int COUT,int HIN,int WIN,int HOUT,int WOUT,int NTHR,int P,int BNIN>
__global__ __launch_bounds__(NTHR)
void conv_smem_kernel(const float* __restrict__ in, const float* __restrict__ w,
                      const float* __restrict__ bias,
                      const float* __restrict__ scale, const float* __restrict__ shift,
                      float* __restrict__ out) {
    __shared__ float plane[HIN*WIN];
    __shared__ float wsm[COUT*9];
    const int b = blockIdx.x;
    const int tid = threadIdx.x;

    float acc[P][COUT];
    #pragma unroll
    for (int p = 0; p < P; p++)
        #pragma unroll
        for (int co = 0; co < COUT; co++) acc[p][co] = 0.f;

    for (int ci = 0; ci < CIN; ci++) {
        __syncthreads();
        const float* ip = in + ((size_t)(b*CIN + ci)) * (HIN*WIN);
        float sc = BNIN ? scale[ci] : 1.f;
        float sh = BNIN ? shift[ci] : 0.f;
        for (int i = tid; i < HIN*WIN; i += NTHR) plane[i] = ip[i]*sc + sh;
        for (int i = tid; i < COUT*9; i += NTHR) wsm[i] = w[((i/9)*CIN + ci)*9 + (i%9)];
        __syncthreads();

        #pragma unroll
        for (int p = 0; p < P; p++) {
            int pos = tid + p*NTHR;
            if (pos < HOUT*WOUT) {
                int ho = pos / WOUT, wo = pos % WOUT;
                float win[9];
                #pragma unroll
                for (int kh = 0; kh < 3; kh++)
                    #pragma unroll
                    for (int kw = 0; kw < 3; kw++) {
                        int hi = ho*2 - 1 + kh, wi = wo*2 - 1 + kw;
                        win[kh*3+kw] = (hi >= 0 && hi < HIN && wi >= 0 && wi < WIN)
                                       ? plane[hi*WIN + wi] : 0.f;
                    }
                #pragma unroll
                for (int co = 0; co < COUT; co++) {
                    float s = 0.f;
                    #pragma unroll
                    for (int t = 0; t < 9; t++) s += win[t] * wsm[co*9 + t];
                    acc[p][co] += s;
                }
            }
        }
    }
    #pragma unroll
    for (int p = 0; p < P; p++) {
        int pos = tid + p*NTHR;
        if (pos < HOUT*WOUT) {
            #pragma unroll
            for (int co = 0; co < COUT; co++)
                out[((size_t)(b*COUT + co))*(HOUT*WOUT) + pos] = fmaxf(acc[p][co] + bias[co], 0.f);
        }
    }
}

// ---------------- deterministic BN stats ----------------
__global__ void bn_partial(const float* __restrict__ y, int HW, int nsl) {
    int c = blockIdx.x;
    long n = 512L * HW;
    long per = (n + nsl - 1) / nsl;
    long st = (long)blockIdx.y * per;
    long en = st + per; if (en > n) en = n;
    float s = 0.f, s2 = 0.f;
    for (long i = st + threadIdx.x; i < en; i += 256) {
        long b = i / HW, p = i % HW;
        float v = y[((size_t)b*24 + c)*HW + p];
        s += v; s2 += v*v;
    }
    __shared__ float sh[256], sh2[256];
    sh[threadIdx.x] = s; sh2[threadIdx.x] = s2;
    __syncthreads();
    for (int o = 128; o > 0; o >>= 1) {
        if (threadIdx.x < o) { sh[threadIdx.x] += sh[threadIdx.x+o]; sh2[threadIdx.x] += sh2[threadIdx.x+o]; }
        __syncthreads();
    }
    if (threadIdx.x == 0) { g_part1[c*16 + blockIdx.y] = sh[0]; g_part2[c*16 + blockIdx.y] = sh2[0]; }
}
__global__ void bn_finalize(const float* __restrict__ g, const float* __restrict__ beta,
                            int HW, int nsl) {
    int c = threadIdx.x;
    if (c >= 24) return;
    float s = 0.f, s2 = 0.f;
    for (int i = 0; i < nsl; i++) { s += g_part1[c*16+i]; s2 += g_part2[c*16+i]; }
    float n = 512.f * HW;
    float mean = s / n;
    float var = s2 / n - mean*mean;
    float sc = g[c] * rsqrtf(var + EPSV);
    g_scale[c] = sc;
    g_shift[c] = beta[c] - mean * sc;
}

// ---------------- layer-1 factorization (BN4 folded in) ----------------
__global__ void uv_kernel(const float* __restrict__ x4, const float* __restrict__ qst,
                          const float* __restrict__ gw1, const float* __restrict__ gb1,
                          const float* __restrict__ scale, const float* __restrict__ shift,
                          float* __restrict__ U, float* __restrict__ V) {
    int idx = blockIdx.x * blockDim.x + threadIdx.x;
    if (idx >= 512*25*256) return;
    int k = idx & 255;
    int t = idx >> 8;
    int pos = t % 25;
    int b = t / 25;

    float cx = ((float)pos / 5.0f - 2.0f) * 0.5f;
    float cy = ((float)(pos % 5) - 2.0f) * 0.5f;

    const float* xr = x4 + (size_t)b*24*25 + pos;
    const float* w  = gw1 + (size_t)k * 63;

    float u = 0.f, v = 0.f;
    #pragma unroll
    for (int ch = 0; ch < 24; ch++) {
        float xv = xr[ch*25]*scale[ch] + shift[ch];
        u += xv * w[ch];
        v += xv * w[26 + ch];
    }
    u += cx * w[24] + cy * w[25];
    v += cx * w[50] + cy * w[51];
    #pragma unroll
    for (int q = 0; q < 11; q++) v += qst[b*11 + q] * w[52 + q];
    v += gb1[k];
    U[idx] = u;
    V[idx] = v;
}

// ---------------- tf32 mma.sync GEMM ----------------
// C[M,256] = relu(A[M,256] @ W[256,256]^T + bias)
// Block 128x128, BK=32, 256 threads, warp tile 32x64 (m16n8k8 tf32).
__device__ __forceinline__ uint32_t to_tf32(float f) {
    uint32_t r;
    asm("cvt.rna.tf32.f32 %0, %1;" : "=r"(r) : "f"(f));
    return r;
}
__device__ __forceinline__ void mma_tf32(float* d, const uint32_t* a, const uint32_t* b) {
    asm volatile(
        "mma.sync.aligned.m16n8k8.row.col.f32.tf32.tf32.f32 "
        "{%0,%1,%2,%3}, {%4,%5,%6,%7}, {%8,%9}, {%0,%1,%2,%3};"
        : "+f"(d[0]), "+f"(d[1]), "+f"(d[2]), "+f"(d[3])
        : "r"(a[0]), "r"(a[1]), "r"(a[2]), "r"(a[3]), "r"(b[0]), "r"(b[1]));
}

#define LDW 36   // padded row length in floats

template<int FUSE_H1>
__global__ __launch_bounds__(256)
void gemm_mma(const float* __restrict__ A, const float* __restrict__ U,
              const float* __restrict__ V, const float* __restrict__ W,
              const float* __restrict__ bias, float* __restrict__ C) {
    extern __shared__ float sm[];
    float* As = sm;                 // [2][128][LDW]
    float* Bs = sm + 2*128*LDW;     // [2][128][LDW]

    const int tid = threadIdx.x;
    const int wid = tid >> 5, lane = tid & 31;
    const int wm = (wid & 3) * 32;
    const int wn = (wid >> 2) * 64;
    const int qr = lane >> 2;   // 0..7
    const int qc = lane & 3;    // 0..3
    const int r0 = blockIdx.y * 128;
    const int n0 = blockIdx.x * 128;

    // staging offsets (constant per thread across k-chunks)
    int uo[4], vo[4], ao[4], wo2[4], so[4];
    #pragma unroll
    for (int it = 0; it < 4; it++) {
        int linear = it*256 + tid;
        int rl = linear >> 3;
        int kc = (linear & 7) * 4;
        so[it] = rl*LDW + kc;
        if (FUSE_H1) {
            int grow = r0 + rl;
            int b = grow / 625;
            int rem = grow - b*625;
            int a = rem / 25;
            int cc = rem - a*25;
            uo[it] = (b*25 + cc)*256 + kc;
            vo[it] = (b*25 + a)*256 + kc;
            ao[it] = 0;
        } else {
            ao[it] = (r0 + rl)*256 + kc;
            uo[it] = vo[it] = 0;
        }
        wo2[it] = (n0 + rl)*256 + kc;
    }

    float acc[2][8][4];
    #pragma unroll
    for (int mf = 0; mf < 2; mf++)
        #pragma unroll
        for (int nf = 0; nf < 8; nf++)
            #pragma unroll
            for (int i = 0; i < 4; i++) acc[mf][nf][i] = 0.f;

    float4 stA[4], stB[4];

    // preload k-chunk 0
    #pragma unroll
    for (int it = 0; it < 4; it++) {
        if (FUSE_H1) {
            float4 u = *(const float4*)(U + uo[it]);
            float4 v = *(const float4*)(V + vo[it]);
            stA[it].x = fmaxf(u.x+v.x, 0.f); stA[it].y = fmaxf(u.y+v.y, 0.f);
            stA[it].z = fmaxf(u.z+v.z, 0.f); stA[it].w = fmaxf(u.w+v.w, 0.f);
        } else {
            stA[it] = *(const float4*)(A + ao[it]);
        }
        stB[it] = *(const float4*)(W + wo2[it]);
    }
    #pragma unroll
    for (int it = 0; it < 4; it++) {
        uint32_t* pa = (uint32_t*)(As + so[it]);
        pa[0]=to_tf32(stA[it].x); pa[1]=to_tf32(stA[it].y); pa[2]=to_tf32(stA[it].z); pa[3]=to_tf32(stA[it].w);
        uint32_t* pb = (uint32_t*)(Bs + so[it]);
        pb[0]=to_tf32(stB[it].x); pb[1]=to_tf32(stB[it].y); pb[2]=to_tf32(stB[it].z); pb[3]=to_tf32(stB[it].w);
    }
    __syncthreads();

    for (int kb = 0; kb < 8; kb++) {
        const int cur = kb & 1;
        // prefetch next chunk into regs
        if (kb < 7) {
            int k0 = (kb+1)*32;
            #pragma unroll
            for (int it = 0; it < 4; it++) {
                if (FUSE_H1) {
                    float4 u = *(const float4*)(U + uo[it] + k0);
                    float4 v = *(const float4*)(V + vo[it] + k0);
                    stA[it].x = fmaxf(u.x+v.x, 0.f); stA[it].y = fmaxf(u.y+v.y, 0.f);
                    stA[it].z = fmaxf(u.z+v.z, 0.f); stA[it].w = fmaxf(u.w+v.w, 0.f);
                } else {
                    stA[it] = *(const float4*)(A + ao[it] + k0);
                }
                stB[it] = *(const float4*)(W + wo2[it] + k0);
            }
        }

        // compute on buffer cur
        const float* Ac = As + cur*128*LDW;
        const float* Bc = Bs + cur*128*LDW;
        #pragma unroll
        for (int ks = 0; ks < 4; ks++) {
            uint32_t af[2][4];
            #pragma unroll
            for (int mf = 0; mf < 2; mf++) {
                int base = (wm + mf*16 + qr)*LDW + ks*8 + qc;
                af[mf][0] = __float_as_uint(Ac[base]);
                af[mf][1] = __float_as_uint(Ac[base + 8*LDW]);
                af[mf][2] = __float_as_uint(Ac[base + 4]);
                af[mf][3] = __float_as_uint(Ac[base + 8*LDW + 4]);
            }
            uint32_t bf[8][2];
            #pragma unroll
            for (int nf = 0; nf < 8; nf++) {
                int base = (wn + nf*8 + qr)*LDW + ks*8 + qc;
                bf[nf][0] = __float_as_uint(Bc[base]);
                bf[nf][1] = __float_as_uint(Bc[base + 4]);
            }
            #pragma unroll
            for (int mf = 0; mf < 2; mf++)
                #pragma unroll
                for (int nf = 0; nf < 8; nf++)
                    mma_tf32(acc[mf][nf], af[mf], bf[nf]);
        }

        if (kb < 7) {
            float* An = As + (1-cur)*128*LDW;
            float* Bn = Bs + (1-cur)*128*LDW;
            #pragma unroll
            for (int it = 0; it < 4; it++) {
                uint32_t* pa = (uint32_t*)(An + so[it]);
                pa[0]=to_tf32(stA[it].x); pa[1]=to_tf32(stA[it].y); pa[2]=to_tf32(stA[it].z); pa[3]=to_tf32(stA[it].w);
                uint32_t* pb = (uint32_t*)(Bn + so[it]);
                pb[0]=to_tf32(stB[it].x); pb[1]=to_tf32(stB[it].y); pb[2]=to_tf32(stB[it].z); pb[3]=to_tf32(stB[it].w);
            }
            __syncthreads();
        }
    }

    // epilogue: bias + relu, float2 stores
    #pragma unroll
    for (int nf = 0; nf < 8; nf++) {
        int n = n0 + wn + nf*8 + qc*2;
        float b0 = bias[n], b1 = bias[n+1];
        #pragma unroll
        for (int mf = 0; mf < 2; mf++) {
            int m = r0 + wm + mf*16 + qr;
            float2 v0, v1;
            v0.x = fmaxf(acc[mf][nf][0] + b0, 0.f);
            v0.y = fmaxf(acc[mf][nf][1] + b1, 0.f);
            v1.x = fmaxf(acc[mf][nf][2] + b0, 0.f);
            v1.y = fmaxf(acc[mf][nf][3] + b1, 0.f);
            *(float2*)(C + (size_t)m*256 + n) = v0;
            *(float2*)(C + (size_t)(m+8)*256 + n) = v1;
        }
    }
}

// ---------------- SIMT GEMM for tiny f-layers ----------------
template<int RELU>
__global__ void gemm_bias_kernel(const float* __restrict__ A, const float* __restrict__ W,
                                 const float* __restrict__ bias, float* __restrict__ C,
                                 int M, int N, int K) {
    __shared__ float As[16][65];
    __shared__ float Bs[16][65];
    const int bm = blockIdx.y * 64;
    const int bn = blockIdx.x * 64;
    const int tid = threadIdx.x;
    const int tx = tid & 15;
    const int ty = tid >> 4;
    const int lrow = tid >> 2;
    const int lcol = (tid & 3) * 4;

    float acc[4][4];
    #pragma unroll
    for (int i = 0; i < 4; i++)
        #pragma unroll
        for (int j = 0; j < 4; j++) acc[i][j] = 0.f;

    for (int k0 = 0; k0 < K; k0 += 16) {
        float4 av = make_float4(0.f,0.f,0.f,0.f);
        if (bm + lrow < M) av = *(const float4*)(A + (size_t)(bm+lrow)*K + k0 + lcol);
        As[lcol+0][lrow]=av.x; As[lcol+1][lrow]=av.y; As[lcol+2][lrow]=av.z; As[lcol+3][lrow]=av.w;
        float4 bv = make_float4(0.f,0.f,0.f,0.f);
        if (bn + lrow < N) bv = *(const float4*)(W + (size_t)(bn+lrow)*K + k0 + lcol);
        Bs[lcol+0][lrow]=bv.x; Bs[lcol+1][lrow]=bv.y; Bs[lcol+2][lrow]=bv.z; Bs[lcol+3][lrow]=bv.w;
        __syncthreads();
        #pragma unroll
        for (int kk = 0; kk < 16; kk++) {
            float a[4], b[4];
            #pragma unroll
            for (int i = 0; i < 4; i++) a[i] = As[kk][ty*4+i];
            #pragma unroll
            for (int j = 0; j < 4; j++) b[j] = Bs[kk][tx*4+j];
            #pragma unroll
            for (int i = 0; i < 4; i++)
                #pragma unroll
                for (int j = 0; j < 4; j++) acc[i][j] += a[i]*b[j];
        }
        __syncthreads();
    }
    #pragma unroll
    for (int i = 0; i < 4; i++) {
        int m = bm + ty*4 + i;
        if (m >= M) continue;
        #pragma unroll
        for (int j = 0; j < 4; j++) {
            int n = bn + tx*4 + j;
            if (n >= N) continue;
            float v = acc[i][j] + bias[n];
            if (RELU) v = fmaxf(v, 0.f);
            C[(size_t)m*N + n] = v;
        }
    }
}

// ---------------- sum pooling ----------------
__global__ void sumpool_kernel(const float* __restrict__ H, float* __restrict__ XG) {
    int b = blockIdx.x;
    int k = threadIdx.x;
    const float* p = H + (size_t)b * 625 * 256 + k;
    float s = 0.f;
    for (int i = 0; i < 625; i++) s += p[(size_t)i * 256];
    XG[b*256 + k] = s;
}

// ---------------- log_softmax ----------------
__global__ void logsoftmax_kernel(const float* __restrict__ in, float* __restrict__ out) {
    int b = blockIdx.x * blockDim.x + threadIdx.x;
    if (b >= 512) return;
    float v[10];
    float m = -1e30f;
    #pragma unroll
    for (int i = 0; i < 10; i++) { v[i] = in[b*10+i]; m = fmaxf(m, v[i]); }
    float s = 0.f;
    #pragma unroll
    for (int i = 0; i < 10; i++) s += expf(v[i] - m);
    float ls = logf(s) + m;
    #pragma unroll
    for (int i = 0; i < 10; i++) out[b*10+i] = v[i] - ls;
}

// ---------------- launch ----------------
extern "C" void kernel_launch(void* const* d_in, const int* in_sizes, int n_in,
                              void* d_out, int out_size) {
    const float* img  = (const float*)d_in[0];
    const float* qst  = (const float*)d_in[1];
    const float* c1w  = (const float*)d_in[2];
    const float* c1b  = (const float*)d_in[3];
    const float* bn1g = (const float*)d_in[4];
    const float* bn1b = (const float*)d_in[5];
    const float* c2w  = (const float*)d_in[6];
    const float* c2b  = (const float*)d_in[7];
    const float* bn2g = (const float*)d_in[8];
    const float* bn2b = (const float*)d_in[9];
    const float* c3w  = (const float*)d_in[10];
    const float* c3b  = (const float*)d_in[11];
    const float* bn3g = (const float*)d_in[12];
    const float* bn3b = (const float*)d_in[13];
    const float* c4w  = (const float*)d_in[14];
    const float* c4b  = (const float*)d_in[15];
    const float* bn4g = (const float*)d_in[16];
    const float* bn4b = (const float*)d_in[17];
    const float* gw1  = (const float*)d_in[18];
    const float* gb1  = (const float*)d_in[19];
    const float* gw2  = (const float*)d_in[20];
    const float* gb2  = (const float*)d_in[21];
    const float* gw3  = (const float*)d_in[22];
    const float* gb3  = (const float*)d_in[23];
    const float* gw4  = (const float*)d_in[24];
    const float* gb4  = (const float*)d_in[25];
    const float* fw1  = (const float*)d_in[26];
    const float* fb1  = (const float*)d_in[27];
    const float* fw2  = (const float*)d_in[28];
    const float* fb2  = (const float*)d_in[29];
    const float* fw3  = (const float*)d_in[30];
    const float* fb3  = (const float*)d_in[31];
    float* out = (float*)d_out;

    float *buf1,*buf2,*buf3,*buf4,*scale,*shift,*U,*V,*HA,*HB,*XG,*F1,*F2,*FO;
    cudaGetSymbolAddress((void**)&buf1, g_buf1);
    cudaGetSymbolAddress((void**)&buf2, g_buf2);
    cudaGetSymbolAddress((void**)&buf3, g_buf3);
    cudaGetSymbolAddress((void**)&buf4, g_buf4);
    cudaGetSymbolAddress((void**)&scale, g_scale);
    cudaGetSymbolAddress((void**)&shift, g_shift);
    cudaGetSymbolAddress((void**)&U, g_U);
    cudaGetSymbolAddress((void**)&V, g_V);
    cudaGetSymbolAddress((void**)&HA, g_HA);
    cudaGetSymbolAddress((void**)&HB, g_HB);
    cudaGetSymbolAddress((void**)&XG, g_XG);
    cudaGetSymbolAddress((void**)&F1, g_F1);
    cudaGetSymbolAddress((void**)&F2, g_F2);
    cudaGetSymbolAddress((void**)&FO, g_FO);

    const int GEMM_SMEM = 2*128*LDW*4*2;   // 73728 bytes
    cudaFuncSetAttribute(gemm_mma<1>, cudaFuncAttributeMaxDynamicSharedMemorySize, GEMM_SMEM);
    cudaFuncSetAttribute(gemm_mma<0>, cudaFuncAttributeMaxDynamicSharedMemorySize, GEMM_SMEM);

    // conv1: img -> buf1 [512,24,38,38]  (no BN on input)
    conv_smem_kernel<3,24,75,75,38,38,768,2,0><<<512,768>>>(img, c1w, c1b, scale, shift, buf1);
    bn_partial<<<dim3(24,16),256>>>(buf1, 38*38, 16);
    bn_finalize<<<1,32>>>(bn1g, bn1b, 38*38, 16);

    // conv2 (applies bn1 to input): buf1 -> buf2 [512,24,19,19]
    conv_smem_kernel<24,24,38,38,19,19,384,1,1><<<512,384>>>(buf1, c2w, c2b, scale, shift, buf2);
    bn_partial<<<dim3(24,8),256>>>(buf2, 19*19, 8);
    bn_finalize<<<1,32>>>(bn2g, bn2b, 19*19, 8);

    // conv3: buf2 -> buf3 [512,24,10,10]
    conv_smem_kernel<24,24,19,19,10,10,128,1,1><<<512,128>>>(buf2, c3w, c3b, scale, shift, buf3);
    bn_partial<<<dim3(24,4),256>>>(buf3, 10*10, 4);
    bn_finalize<<<1,32>>>(bn3g, bn3b, 10*10, 4);

    // conv4: buf3 -> buf4 [512,24,5,5]
    conv_smem_kernel<24,24,10,10,5,5,64,1,1><<<512,64>>>(buf3, c4w, c4b, scale, shift, buf4);
    bn_partial<<<dim3(24,2),256>>>(buf4, 5*5, 2);
    bn_finalize<<<1,32>>>(bn4g, bn4b, 5*5, 2);

    // g layer 1 factorized (bn4 folded in)
    {
        int total = 512*25*256;
        uv_kernel<<<(total+255)/256, 256>>>(buf4, qst, gw1, gb1, scale, shift, U, V);
    }

    // g layers 2-4 on tensor cores (layer 2 fuses h1 construction)
    {
        dim3 grid(2, 2500), block(256);
        gemm_mma<1><<<grid, block, GEMM_SMEM>>>(nullptr, U, V, gw2, gb2, HA);
        gemm_mma<0><<<grid, block, GEMM_SMEM>>>(HA, nullptr, nullptr, gw3, gb3, HB);
        gemm_mma<0><<<grid, block, GEMM_SMEM>>>(HB, nullptr, nullptr, gw4, gb4, HA);
    }

    // sum pooling over 625 pairs
    sumpool_kernel<<<512, 256>>>(HA, XG);

    // f layers (tiny)
    {
        dim3 grid(4, 8), block(256);
        gemm_bias_kernel<1><<<grid, block>>>(XG, fw1, fb1, F1, 512, 256, 256);
        gemm_bias_kernel<1><<<grid, block>>>(F1, fw2, fb2, F2, 512, 256, 256);
        dim3 grid3(1, 8);
        gemm_bias_kernel<0><<<grid3, block>>>(F2, fw3, fb3, FO, 512, 10, 256);
    }

    logsoftmax_kernel<<<2, 256>>>(FO, out);
}

// round 5
// speedup vs baseline: 4.4967x; 1.4180x over previous
#include <cuda_runtime.h>
#include <math.h>
#include <stdint.h>

#define EPSV 1e-5f

// ---------------- static scratch ----------------
__device__ float g_buf1[512*24*38*38];
__device__ float g_buf2[512*24*19*19];
__device__ float g_buf3[512*24*10*10];
__device__ float g_buf4[512*24*5*5];
__device__ float g_part1[24*16];
__device__ float g_part2[24*16];
__device__ float g_scale[24];
__device__ float g_shift[24];
__device__ float g_U[512*25*256];
__device__ float g_V[512*25*256];
__device__ float g_HA[320000u*256];
__device__ float g_HB[320000u*256];
__device__ float g_W2[65536];
__device__ float g_W3[65536];
__device__ float g_W4[65536];
__device__ float g_XG[512*256];
__device__ float g_F1[512*256];
__device__ float g_F2[512*256];
__device__ float g_FO[512*10];

// ---------------- helpers ----------------
__device__ __forceinline__ uint32_t smem_u32(const void* p) {
    uint32_t a;
    asm("{ .reg .u64 t; cvta.to.shared.u64 t, %1; cvt.u32.u64 %0, t; }" : "=r"(a) : "l"(p));
    return a;
}
__device__ __forceinline__ void cp_async16(uint32_t dst, const void* src) {
    asm volatile("cp.async.cg.shared.global [%0], [%1], 16;" :: "r"(dst), "l"(src));
}
__device__ __forceinline__ void cp_async4(uint32_t dst, const void* src) {
    asm volatile("cp.async.ca.shared.global [%0], [%1], 4;" :: "r"(dst), "l"(src));
}
__device__ __forceinline__ void cp_commit() { asm volatile("cp.async.commit_group;"); }
__device__ __forceinline__ void cp_wait0() { asm volatile("cp.async.wait_group 0;"); }
__device__ __forceinline__ void cp_wait1() { asm volatile("cp.async.wait_group 1;"); }

__device__ __forceinline__ uint32_t to_tf32(float f) {
    uint32_t r;
    asm("cvt.rna.tf32.f32 %0, %1;" : "=r"(r) : "f"(f));
    return r;
}
__device__ __forceinline__ float round_tf32f(float f) { return __uint_as_float(to_tf32(f)); }

__device__ __forceinline__ void mma_tf32(float* d, const uint32_t* a, const uint32_t* b) {
    asm volatile(
        "mma.sync.aligned.m16n8k8.row.col.f32.tf32.tf32.f32 "
        "{%0,%1,%2,%3}, {%4,%5,%6,%7}, {%8,%9}, {%0,%1,%2,%3};"
        : "+f"(d[0]), "+f"(d[1]), "+f"(d[2]), "+f"(d[3])
        : "r"(a[0]), "r"(a[1]), "r"(a[2]), "r"(a[3]), "r"(b[0]), "r"(b[1]));
}

// ---------------- weight pre-rounding to tf32 ----------------
__global__ void round_w_kernel(const float* __restrict__ in, float* __restrict__ out, int n) {
    int i = blockIdx.x * blockDim.x + threadIdx.x;
    if (i < n) out[i] = round_tf32f(in[i]);
}

// ---------------- conv: cp.async double-buffered planes, all weights resident ----------------
template<int CIN,int COUT,int HIN,int WIN,int HOUT,int WOUT,int NTHR,int P,int BNIN>
__global__ __launch_bounds__(NTHR)
void conv_pipe_kernel(const float* __restrict__ in, const float* __restrict__ w,
                      const float* __restrict__ bias,
                      const float* __restrict__ scale, const float* __restrict__ shift,
                      float* __restrict__ out) {
    __shared__ float plane[2][HIN*WIN];
    __shared__ float wsm[CIN*COUT*9];
    const int b = blockIdx.x;
    const int tid = threadIdx.x;
    const int HW = HIN*WIN;
    const uint32_t pa[2] = { smem_u32(&plane[0][0]), smem_u32(&plane[1][0]) };
    const float* ip = in + (size_t)b*CIN*HW;

    for (int i = tid; i < CIN*COUT*9; i += NTHR) {
        int ci = i / (COUT*9), r = i % (COUT*9);
        int co = r / 9, t = r % 9;
        wsm[i] = w[(co*CIN + ci)*9 + t];
    }
    for (int i = tid; i < HW; i += NTHR) cp_async4(pa[0] + i*4, ip + i);
    cp_commit();

    float acc[P][COUT];
    #pragma unroll
    for (int p = 0; p < P; p++)
        #pragma unroll
        for (int co = 0; co < COUT; co++) acc[p][co] = 0.f;

    for (int ci = 0; ci < CIN; ci++) {
        if (ci + 1 < CIN) {
            const float* nip = ip + (size_t)(ci+1)*HW;
            uint32_t pd = pa[(ci+1)&1];
            for (int i = tid; i < HW; i += NTHR) cp_async4(pd + i*4, nip + i);
            cp_commit();
            cp_wait1();
        } else {
            cp_wait0();
        }
        __syncthreads();

        const float sc = BNIN ? scale[ci] : 1.f;
        const float sh = BNIN ? shift[ci] : 0.f;
        const float* pl = plane[ci&1];
        const float* wp = wsm + ci*(COUT*9);

        #pragma unroll
        for (int p = 0; p < P; p++) {
            int pos = tid + p*NTHR;
            if (pos < HOUT*WOUT) {
                int ho = pos / WOUT, wo = pos % WOUT;
                float win[9];
                #pragma unroll
                for (int kh = 0; kh < 3; kh++)
                    #pragma unroll
                    for (int kw = 0; kw < 3; kw++) {
                        int hi = ho*2 - 1 + kh, wi = wo*2 - 1 + kw;
                        bool inb = (hi >= 0 && hi < HIN && wi >= 0 && wi < WIN);
                        float xv = inb ? pl[hi*WIN + wi] : 0.f;
                        win[kh*3+kw] = (BNIN && inb) ? fmaf(xv, sc, sh) : xv;
                    }
                #pragma unroll
                for (int co = 0; co < COUT; co++) {
                    float s = 0.f;
                    #pragma unroll
                    for (int t = 0; t < 9; t++) s += win[t] * wp[co*9 + t];
                    acc[p][co] += s;
                }
            }
        }
        __syncthreads();
    }
    #pragma unroll
    for (int p = 0; p < P; p++) {
        int pos = tid + p*NTHR;
        if (pos < HOUT*WOUT) {
            #pragma unroll
            for (int co = 0; co < COUT; co++)
                out[((size_t)(b*COUT + co))*(HOUT*WOUT) + pos] = fmaxf(acc[p][co] + bias[co], 0.f);
        }
    }
}

// ---------------- deterministic BN stats ----------------
__global__ void bn_partial(const float* __restrict__ y, int HW, int nsl) {
    int c = blockIdx.x;
    long n = 512L * HW;
    long per = (n + nsl - 1) / nsl;
    long st = (long)blockIdx.y * per;
    long en = st + per; if (en > n) en = n;
    float s = 0.f, s2 = 0.f;
    for (long i = st + threadIdx.x; i < en; i += 256) {
        long b = i / HW, p = i % HW;
        float v = y[((size_t)b*24 + c)*HW + p];
        s += v; s2 += v*v;
    }
    __shared__ float sh[256], sh2[256];
    sh[threadIdx.x] = s; sh2[threadIdx.x] = s2;
    __syncthreads();
    for (int o = 128; o > 0; o >>= 1) {
        if (threadIdx.x < o) { sh[threadIdx.x] += sh[threadIdx.x+o]; sh2[threadIdx.x] += sh2[threadIdx.x+o]; }
        __syncthreads();
    }
    if (threadIdx.x == 0) { g_part1[c*16 + blockIdx.y] = sh[0]; g_part2[c*16 + blockIdx.y] = sh2[0]; }
}
__global__ void bn_finalize(const float* __restrict__ g, const float* __restrict__ beta,
                            int HW, int nsl) {
    int c = threadIdx.x;
    if (c >= 24) return;
    float s = 0.f, s2 = 0.f;
    for (int i = 0; i < nsl; i++) { s += g_part1[c*16+i]; s2 += g_part2[c*16+i]; }
    float n = 512.f * HW;
    float mean = s / n;
    float var = s2 / n - mean*mean;
    float sc = g[c] * rsqrtf(var + EPSV);
    g_scale[c] = sc;
    g_shift[c] = beta[c] - mean * sc;
}

// ---------------- layer-1 factorization: per-image, gw1 resident in SMEM ----------------
__global__ __launch_bounds__(256)
void uv_kernel(const float* __restrict__ x4, const float* __restrict__ qst,
               const float* __restrict__ gw1, const float* __restrict__ gb1,
               const float* __restrict__ scale, const float* __restrict__ shift,
               float* __restrict__ U, float* __restrict__ V) {
    extern __shared__ float us[];
    float* ws = us;            // 256*63
    float* xs = ws + 256*63;   // 24*25 normalized
    float* qs = xs + 600;      // 11
    const int b = blockIdx.x;
    const int k = threadIdx.x;

    for (int i = k; i < 256*63; i += 256) ws[i] = gw1[i];
    for (int i = k; i < 600; i += 256) {
        int ch = i / 25;
        xs[i] = x4[(size_t)b*600 + i] * scale[ch] + shift[ch];
    }
    if (k < 11) qs[k] = qst[b*11 + k];
    __syncthreads();

    const float* w = ws + k*63;
    float vq = gb1[k];
    #pragma unroll
    for (int q = 0; q < 11; q++) vq += qs[q] * w[52 + q];

    for (int pos = 0; pos < 25; pos++) {
        float cx = ((float)pos / 5.0f - 2.0f) * 0.5f;
        float cy = ((float)(pos % 5) - 2.0f) * 0.5f;
        float u = cx * w[24] + cy * w[25];
        float v = vq + cx * w[50] + cy * w[51];
        #pragma unroll
        for (int ch = 0; ch < 24; ch++) {
            float xv = xs[ch*25 + pos];
            u += xv * w[ch];
            v += xv * w[26 + ch];
        }
        U[(size_t)(b*25 + pos)*256 + k] = u;
        V[(size_t)(b*25 + pos)*256 + k] = v;
    }
}

// ---------------- tf32 mma GEMM: C[128-tile, 256] = act(A @ W^T + bias) ----------------
// BM=128, BN=256 (full), BK=32, 256 threads, warps 2m x 4n (warp tile 64x64).
// SMEM: A stages 2x16KB, B stages 2x32KB, XOR-swizzled 128B rows, cp.async staging.
template<int FUSE_H1, int ROUND_OUT>
__global__ __launch_bounds__(256)
void gemm_mma(const float* __restrict__ A, const float* __restrict__ U,
              const float* __restrict__ V, const float* __restrict__ W,
              const float* __restrict__ bias, float* __restrict__ C) {
    extern __shared__ float sm[];
    char* smc = (char*)sm;
    const uint32_t aAddr = smem_u32(sm);
    const uint32_t bAddr = aAddr + 32768;

    const int tid = threadIdx.x;
    const int wid = tid >> 5, lane = tid & 31;
    const int qr = lane >> 2, qc = lane & 3;
    const int wm = (wid & 1) * 64;
    const int wn = (wid >> 1) * 64;
    const int r0 = blockIdx.x * 128;
    const uint32_t sw = qr * 16;

    // cp.async chunk geometry
    int arow[4], aj[4], adst[4];
    #pragma unroll
    for (int it = 0; it < 4; it++) {
        int cid = it*256 + tid;
        arow[it] = cid >> 3; aj[it] = cid & 7;
        adst[it] = arow[it]*128 + ((aj[it]*16) ^ ((arow[it] & 7) * 16));
    }
    int brow[8], bj[8], bdst[8];
    #pragma unroll
    for (int it = 0; it < 8; it++) {
        int cid = it*256 + tid;
        brow[it] = cid >> 3; bj[it] = cid & 7;
        bdst[it] = brow[it]*128 + ((bj[it]*16) ^ ((brow[it] & 7) * 16));
    }
    // FUSE: U/V gather offsets
    int uo[4], vo[4];
    if (FUSE_H1) {
        #pragma unroll
        for (int it = 0; it < 4; it++) {
            int grow = r0 + arow[it];
            int b = grow / 625;
            int rem = grow - b*625;
            int a = rem / 25;
            int cc = rem - a*25;
            uo[it] = (b*25 + cc)*256 + aj[it]*4;
            vo[it] = (b*25 + a)*256 + aj[it]*4;
        }
    }

    float acc[4][8][4];
    #pragma unroll
    for (int mf = 0; mf < 4; mf++)
        #pragma unroll
        for (int nf = 0; nf < 8; nf++)
            #pragma unroll
            for (int i = 0; i < 4; i++) acc[mf][nf][i] = 0.f;

    float4 stA[4];

    // ---- prologue ----
    if (FUSE_H1) {
        #pragma unroll
        for (int it = 0; it < 8; it++)
            cp_async16(bAddr + bdst[it], W + (size_t)brow[it]*256 + bj[it]*4);
        cp_commit();
        #pragma unroll
        for (int it = 0; it < 4; it++) {
            float4 u = *(const float4*)(U + uo[it]);
            float4 v = *(const float4*)(V + vo[it]);
            stA[it].x = fmaxf(u.x+v.x, 0.f); stA[it].y = fmaxf(u.y+v.y, 0.f);
            stA[it].z = fmaxf(u.z+v.z, 0.f); stA[it].w = fmaxf(u.w+v.w, 0.f);
        }
        #pragma unroll
        for (int it = 0; it < 8; it++)
            cp_async16(bAddr + 32768 + bdst[it], W + (size_t)brow[it]*256 + 32 + bj[it]*4);
        cp_commit();
        #pragma unroll
        for (int it = 0; it < 4; it++) {
            uint4 t;
            t.x = to_tf32(stA[it].x); t.y = to_tf32(stA[it].y);
            t.z = to_tf32(stA[it].z); t.w = to_tf32(stA[it].w);
            *(uint4*)(smc + adst[it]) = t;
        }
        cp_wait1();
        __syncthreads();
    } else {
        #pragma unroll
        for (int it = 0; it < 4; it++)
            cp_async16(aAddr + adst[it], A + (size_t)(r0 + arow[it])*256 + aj[it]*4);
        #pragma unroll
        for (int it = 0; it < 8; it++)
            cp_async16(bAddr + bdst[it], W + (size_t)brow[it]*256 + bj[it]*4);
        cp_commit();
        #pragma unroll
        for (int it = 0; it < 4; it++)
            cp_async16(aAddr + 16384 + adst[it], A + (size_t)(r0 + arow[it])*256 + 32 + aj[it]*4);
        #pragma unroll
        for (int it = 0; it < 8; it++)
            cp_async16(bAddr + 32768 + bdst[it], W + (size_t)brow[it]*256 + 32 + bj[it]*4);
        cp_commit();
        cp_wait1();
        __syncthreads();
    }

    // ---- main loop over 8 k-chunks ----
    for (int kb = 0; kb < 8; kb++) {
        const int stg = kb & 1;

        if (FUSE_H1 && kb < 7) {
            int k0 = (kb+1)*32;
            #pragma unroll
            for (int it = 0; it < 4; it++) {
                float4 u = *(const float4*)(U + uo[it] + k0);
                float4 v = *(const float4*)(V + vo[it] + k0);
                stA[it].x = fmaxf(u.x+v.x, 0.f); stA[it].y = fmaxf(u.y+v.y, 0.f);
                stA[it].z = fmaxf(u.z+v.z, 0.f); stA[it].w = fmaxf(u.w+v.w, 0.f);
            }
        }

        // compute
        {
            const char* Ab = smc + stg*16384;
            const char* Bb = smc + 32768 + stg*32768;
            #pragma unroll
            for (int ks = 0; ks < 4; ks++) {
                const uint32_t fa = ks*32 + qc*4;
                const uint32_t o0 = fa ^ sw;
                const uint32_t o1 = (fa + 16) ^ sw;
                uint32_t af[4][4];
                #pragma unroll
                for (int mf = 0; mf < 4; mf++) {
                    const char* p = Ab + (wm + mf*16 + qr)*128;
                    af[mf][0] = *(const uint32_t*)(p + o0);
                    af[mf][1] = *(const uint32_t*)(p + 1024 + o0);
                    af[mf][2] = *(const uint32_t*)(p + o1);
                    af[mf][3] = *(const uint32_t*)(p + 1024 + o1);
                }
                uint32_t bf[8][2];
                #pragma unroll
                for (int nf = 0; nf < 8; nf++) {
                    const char* p = Bb + (wn + nf*8 + qr)*128;
                    bf[nf][0] = *(const uint32_t*)(p + o0);
                    bf[nf][1] = *(const uint32_t*)(p + o1);
                }
                #pragma unroll
                for (int mf = 0; mf < 4; mf++)
                    #pragma unroll
                    for (int nf = 0; nf < 8; nf++)
                        mma_tf32(acc[mf][nf], af[mf], bf[nf]);
            }
        }
        __syncthreads();

        if (FUSE_H1) {
            if (kb < 7) {
                #pragma unroll
                for (int it = 0; it < 4; it++) {
                    uint4 t;
                    t.x = to_tf32(stA[it].x); t.y = to_tf32(stA[it].y);
                    t.z = to_tf32(stA[it].z); t.w = to_tf32(stA[it].w);
                    *(uint4*)(smc + ((kb+1)&1)*16384 + adst[it]) = t;
                }
            }
            if (kb < 6) {
                int k0 = (kb+2)*32;
                #pragma unroll
                for (int it = 0; it < 8; it++)
                    cp_async16(bAddr + stg*32768 + bdst[it], W + (size_t)brow[it]*256 + k0 + bj[it]*4);
                cp_commit();
                cp_wait1();
            } else if (kb == 6) {
                cp_wait0();
            }
            if (kb < 7) __syncthreads();
        } else {
            if (kb < 6) {
                int k0 = (kb+2)*32;
                #pragma unroll
                for (int it = 0; it < 4; it++)
                    cp_async16(aAddr + stg*16384 + adst[it], A + (size_t)(r0 + arow[it])*256 + k0 + aj[it]*4);
                #pragma unroll
                for (int it = 0; it < 8; it++)
                    cp_async16(bAddr + stg*32768 + bdst[it], W + (size_t)brow[it]*256 + k0 + bj[it]*4);
                cp_commit();
                cp_wait1();
                __syncthreads();
            } else if (kb == 6) {
                cp_wait0();
                __syncthreads();
            }
        }
    }

    // ---- epilogue ----
    #pragma unroll
    for (int nf = 0; nf < 8; nf++) {
        int n = wn + nf*8 + qc*2;
        float b0 = bias[n], b1 = bias[n+1];
        #pragma unroll
        for (int mf = 0; mf < 4; mf++) {
            int m = r0 + wm + mf*16 + qr;
            float2 v0, v1;
            v0.x = fmaxf(acc[mf][nf][0] + b0, 0.f);
            v0.y = fmaxf(acc[mf][nf][1] + b1, 0.f);
            v1.x = fmaxf(acc[mf][nf][2] + b0, 0.f);
            v1.y = fmaxf(acc[mf][nf][3] + b1, 0.f);
            if (ROUND_OUT) {
                v0.x = round_tf32f(v0.x); v0.y = round_tf32f(v0.y);
                v1.x = round_tf32f(v1.x); v1.y = round_tf32f(v1.y);
            }
            *(float2*)(C + (size_t)m*256 + n) = v0;
            *(float2*)(C + (size_t)(m+8)*256 + n) = v1;
        }
    }
}

// ---------------- SIMT GEMM for tiny f-layers ----------------
template<int RELU>
__global__ void gemm_bias_kernel(const float* __restrict__ A, const float* __restrict__ W,
                                 const float* __restrict__ bias, float* __restrict__ C,
                                 int M, int N, int K) {
    __shared__ float As[16][65];
    __shared__ float Bs[16][65];
    const int bm = blockIdx.y * 64;
    const int bn = blockIdx.x * 64;
    const int tid = threadIdx.x;
    const int tx = tid & 15;
    const int ty = tid >> 4;
    const int lrow = tid >> 2;
    const int lcol = (tid & 3) * 4;

    float acc[4][4];
    #pragma unroll
    for (int i = 0; i < 4; i++)
        #pragma unroll
        for (int j = 0; j < 4; j++) acc[i][j] = 0.f;

    for (int k0 = 0; k0 < K; k0 += 16) {
        float4 av = make_float4(0.f,0.f,0.f,0.f);
        if (bm + lrow < M) av = *(const float4*)(A + (size_t)(bm+lrow)*K + k0 + lcol);
        As[lcol+0][lrow]=av.x; As[lcol+1][lrow]=av.y; As[lcol+2][lrow]=av.z; As[lcol+3][lrow]=av.w;
        float4 bv = make_float4(0.f,0.f,0.f,0.f);
        if (bn + lrow < N) bv = *(const float4*)(W + (size_t)(bn+lrow)*K + k0 + lcol);
        Bs[lcol+0][lrow]=bv.x; Bs[lcol+1][lrow]=bv.y; Bs[lcol+2][lrow]=bv.z; Bs[lcol+3][lrow]=bv.w;
        __syncthreads();
        #pragma unroll
        for (int kk = 0; kk < 16; kk++) {
            float a[4], b[4];
            #pragma unroll
            for (int i = 0; i < 4; i++) a[i] = As[kk][ty*4+i];
            #pragma unroll
            for (int j = 0; j < 4; j++) b[j] = Bs[kk][tx*4+j];
            #pragma unroll
            for (int i = 0; i < 4; i++)
                #pragma unroll
                for (int j = 0; j < 4; j++) acc[i][j] += a[i]*b[j];
        }
        __syncthreads();
    }
    #pragma unroll
    for (int i = 0; i < 4; i++) {
        int m = bm + ty*4 + i;
        if (m >= M) continue;
        #pragma unroll
        for (int j = 0; j < 4; j++) {
            int n = bn + tx*4 + j;
            if (n >= N) continue;
            float v = acc[i][j] + bias[n];
            if (RELU) v = fmaxf(v, 0.f);
            C[(size_t)m*N + n] = v;
        }
    }
}

// ---------------- sum pooling (float4) ----------------
__global__ __launch_bounds__(256)
void sumpool_kernel(const float* __restrict__ H, float* __restrict__ XG) {
    __shared__ float4 red[4][64];
    const int b = blockIdx.x;
    const int t = threadIdx.x;
    const int kq = (t & 63) * 4;
    const int rg = t >> 6;
    float4 s = make_float4(0.f, 0.f, 0.f, 0.f);
    const float* base = H + (size_t)b * 625 * 256 + kq;
    for (int i = rg; i < 625; i += 4) {
        float4 v = *(const float4*)(base + (size_t)i * 256);
        s.x += v.x; s.y += v.y; s.z += v.z; s.w += v.w;
    }
    red[rg][t & 63] = s;
    __syncthreads();
    if (t < 64) {
        float4 a = red[0][t], b1 = red[1][t], c = red[2][t], d = red[3][t];
        a.x += b1.x + c.x + d.x; a.y += b1.y + c.y + d.y;
        a.z += b1.z + c.z + d.z; a.w += b1.w + c.w + d.w;
        *(float4*)(XG + b*256 + t*4) = a;
    }
}

// ---------------- log_softmax ----------------
__global__ void logsoftmax_kernel(const float* __restrict__ in, float* __restrict__ out) {
    int b = blockIdx.x * blockDim.x + threadIdx.x;
    if (b >= 512) return;
    float v[10];
    float m = -1e30f;
    #pragma unroll
    for (int i = 0; i < 10; i++) { v[i] = in[b*10+i]; m = fmaxf(m, v[i]); }
    float s = 0.f;
    #pragma unroll
    for (int i = 0; i < 10; i++) s += expf(v[i] - m);
    float ls = logf(s) + m;
    #pragma unroll
    for (int i = 0; i < 10; i++) out[b*10+i] = v[i] - ls;
}

// ---------------- launch ----------------
extern "C" void kernel_launch(void* const* d_in, const int* in_sizes, int n_in,
                              void* d_out, int out_size) {
    const float* img  = (const float*)d_in[0];
    const float* qst  = (const float*)d_in[1];
    const float* c1w  = (const float*)d_in[2];
    const float* c1b  = (const float*)d_in[3];
    const float* bn1g = (const float*)d_in[4];
    const float* bn1b = (const float*)d_in[5];
    const float* c2w  = (const float*)d_in[6];
    const float* c2b  = (const float*)d_in[7];
    const float* bn2g = (const float*)d_in[8];
    const float* bn2b = (const float*)d_in[9];
    const float* c3w  = (const float*)d_in[10];
    const float* c3b  = (const float*)d_in[11];
    const float* bn3g = (const float*)d_in[12];
    const float* bn3b = (const float*)d_in[13];
    const float* c4w  = (const float*)d_in[14];
    const float* c4b  = (const float*)d_in[15];
    const float* bn4g = (const float*)d_in[16];
    const float* bn4b = (const float*)d_in[17];
    const float* gw1  = (const float*)d_in[18];
    const float* gb1  = (const float*)d_in[19];
    const float* gw2  = (const float*)d_in[20];
    const float* gb2  = (const float*)d_in[21];
    const float* gw3  = (const float*)d_in[22];
    const float* gb3  = (const float*)d_in[23];
    const float* gw4  = (const float*)d_in[24];
    const float* gb4  = (const float*)d_in[25];
    const float* fw1  = (const float*)d_in[26];
    const float* fb1  = (const float*)d_in[27];
    const float* fw2  = (const float*)d_in[28];
    const float* fb2  = (const float*)d_in[29];
    const float* fw3  = (const float*)d_in[30];
    const float* fb3  = (const float*)d_in[31];
    float* out = (float*)d_out;

    float *buf1,*buf2,*buf3,*buf4,*scale,*shift,*U,*V,*HA,*HB,*XG,*F1,*F2,*FO,*W2,*W3,*W4;
    cudaGetSymbolAddress((void**)&buf1, g_buf1);
    cudaGetSymbolAddress((void**)&buf2, g_buf2);
    cudaGetSymbolAddress((void**)&buf3, g_buf3);
    cudaGetSymbolAddress((void**)&buf4, g_buf4);
    cudaGetSymbolAddress((void**)&scale, g_scale);
    cudaGetSymbolAddress((void**)&shift, g_shift);
    cudaGetSymbolAddress((void**)&U, g_U);
    cudaGetSymbolAddress((void**)&V, g_V);
    cudaGetSymbolAddress((void**)&HA, g_HA);
    cudaGetSymbolAddress((void**)&HB, g_HB);
    cudaGetSymbolAddress((void**)&XG, g_XG);
    cudaGetSymbolAddress((void**)&F1, g_F1);
    cudaGetSymbolAddress((void**)&F2, g_F2);
    cudaGetSymbolAddress((void**)&FO, g_FO);
    cudaGetSymbolAddress((void**)&W2, g_W2);
    cudaGetSymbolAddress((void**)&W3, g_W3);
    cudaGetSymbolAddress((void**)&W4, g_W4);

    const int GEMM_SMEM = 98304;
    cudaFuncSetAttribute(gemm_mma<1,1>, cudaFuncAttributeMaxDynamicSharedMemorySize, GEMM_SMEM);
    cudaFuncSetAttribute(gemm_mma<0,1>, cudaFuncAttributeMaxDynamicSharedMemorySize, GEMM_SMEM);
    cudaFuncSetAttribute(gemm_mma<0,0>, cudaFuncAttributeMaxDynamicSharedMemorySize, GEMM_SMEM);
    const int UV_SMEM = (256*63 + 600 + 16) * 4;
    cudaFuncSetAttribute(uv_kernel, cudaFuncAttributeMaxDynamicSharedMemorySize, UV_SMEM);

    // pre-round GEMM weights to tf32 (rna) once
    round_w_kernel<<<256, 256>>>(gw2, W2, 65536);
    round_w_kernel<<<256, 256>>>(gw3, W3, 65536);
    round_w_kernel<<<256, 256>>>(gw4, W4, 65536);

    // conv stack
    conv_pipe_kernel<3,24,75,75,38,38,768,2,0><<<512,768>>>(img, c1w, c1b, scale, shift, buf1);
    bn_partial<<<dim3(24,16),256>>>(buf1, 38*38, 16);
    bn_finalize<<<1,32>>>(bn1g, bn1b, 38*38, 16);

    conv_pipe_kernel<24,24,38,38,19,19,384,1,1><<<512,384>>>(buf1, c2w, c2b, scale, shift, buf2);
    bn_partial<<<dim3(24,8),256>>>(buf2, 19*19, 8);
    bn_finalize<<<1,32>>>(bn2g, bn2b, 19*19, 8);

    conv_pipe_kernel<24,24,19,19,10,10,128,1,1><<<512,128>>>(buf2, c3w, c3b, scale, shift, buf3);
    bn_partial<<<dim3(24,4),256>>>(buf3, 10*10, 4);
    bn_finalize<<<1,32>>>(bn3g, bn3b, 10*10, 4);

    conv_pipe_kernel<24,24,10,10,5,5,64,1,1><<<512,64>>>(buf3, c4w, c4b, scale, shift, buf4);
    bn_partial<<<dim3(24,2),256>>>(buf4, 5*5, 2);
    bn_finalize<<<1,32>>>(bn4g, bn4b, 5*5, 2);

    // g layer 1 factorized (bn4 folded in)
    uv_kernel<<<512, 256, UV_SMEM>>>(buf4, qst, gw1, gb1, scale, shift, U, V);

    // g layers 2-4 (tensor cores; layer 2 fuses h1 construction)
    gemm_mma<1,1><<<2500, 256, GEMM_SMEM>>>(nullptr, U, V, W2, gb2, HA);
    gemm_mma<0,1><<<2500, 256, GEMM_SMEM>>>(HA, nullptr, nullptr, W3, gb3, HB);
    gemm_mma<0,0><<<2500, 256, GEMM_SMEM>>>(HB, nullptr, nullptr, W4, gb4, HA);

    // sum pooling over 625 pairs
    sumpool_kernel<<<512, 256>>>(HA, XG);

    // f layers (tiny)
    {
        dim3 grid(4, 8), block(256);
        gemm_bias_kernel<1><<<grid, block>>>(XG, fw1, fb1, F1, 512, 256, 256);
        gemm_bias_kernel<1><<<grid, block>>>(F1, fw2, fb2, F2, 512, 256, 256);
        dim3 grid3(1, 8);
        gemm_bias_kernel<0><<<grid3, block>>>(F2, fw3, fb3, FO, 512, 10, 256);
    }

    logsoftmax_kernel<<<2, 256>>>(FO, out);
}

// round 6
// speedup vs baseline: 7.7264x; 1.7182x over previous
#include <cuda_runtime.h>
#include <cuda_fp16.h>
#include <math.h>
#include <stdint.h>

#define EPSV 1e-5f

// ---------------- static scratch ----------------
__device__ float g_buf1[512*24*38*38];
__device__ float g_buf2[512*24*19*19];
__device__ float g_buf3[512*24*10*10];
__device__ float g_buf4[512*24*5*5];
__device__ float g_part1[24*16];
__device__ float g_part2[24*16];
__device__ float g_scale[24];
__device__ float g_shift[24];
__device__ float g_U[512*25*256];
__device__ float g_V[512*25*256];
__device__ __half g_W2h[65536];
__device__ __half g_W3h[65536];
__device__ __half g_W4h[65536];
__device__ float g_P[2560*256];
__device__ float g_XG[512*256];
__device__ float g_F1[512*256];
__device__ float g_F2[512*256];
__device__ float g_FO[512*10];

// ---------------- helpers ----------------
__device__ __forceinline__ uint32_t smem_u32(const void* p) {
    uint32_t a;
    asm("{ .reg .u64 t; cvta.to.shared.u64 t, %1; cvt.u32.u64 %0, t; }" : "=r"(a) : "l"(p));
    return a;
}
__device__ __forceinline__ void cp_async16(uint32_t dst, const void* src) {
    asm volatile("cp.async.cg.shared.global [%0], [%1], 16;" :: "r"(dst), "l"(src));
}
__device__ __forceinline__ void cp_commit() { asm volatile("cp.async.commit_group;"); }
__device__ __forceinline__ void cp_wait0() { asm volatile("cp.async.wait_group 0;"); }
__device__ __forceinline__ void cp_wait1() { asm volatile("cp.async.wait_group 1;"); }

__device__ __forceinline__ void mma_f16(float* d, const uint32_t* a, const uint32_t* b) {
    asm volatile(
        "mma.sync.aligned.m16n8k16.row.col.f32.f16.f16.f32 "
        "{%0,%1,%2,%3}, {%4,%5,%6,%7}, {%8,%9}, {%0,%1,%2,%3};"
        : "+f"(d[0]), "+f"(d[1]), "+f"(d[2]), "+f"(d[3])
        : "r"(a[0]), "r"(a[1]), "r"(a[2]), "r"(a[3]), "r"(b[0]), "r"(b[1]));
}

// ---------------- weight conversion fp32 -> fp16 (once) ----------------
__global__ void w_to_half(const float* __restrict__ in, __half* __restrict__ out, int n) {
    int i = blockIdx.x * blockDim.x + threadIdx.x;
    if (i < n) out[i] = __float2half_rn(in[i]);
}

// ---------------- conv: all planes resident, single sync ----------------
template<int CIN,int COUT,int HIN,int WIN,int HOUT,int WOUT,int NTHR,int P,int BNIN,int IMGS>
__global__ __launch_bounds__(NTHR)
void conv_res_kernel(const float* __restrict__ in, const float* __restrict__ w,
                     const float* __restrict__ bias,
                     const float* __restrict__ scale, const float* __restrict__ shift,
                     float* __restrict__ out) {
    extern __shared__ float cs[];
    float* planes = cs;
    float* wsm = cs + IMGS*CIN*HIN*WIN;
    const int tid = threadIdx.x;
    const int HW = HIN*WIN;
    const size_t gbase = (size_t)blockIdx.x * IMGS * CIN * HW;

    for (int i = tid; i < IMGS*CIN*HW; i += NTHR) {
        float v = in[gbase + i];
        if (BNIN) { int ci = (i / HW) % CIN; v = v*scale[ci] + shift[ci]; }
        planes[i] = v;
    }
    for (int i = tid; i < CIN*COUT*9; i += NTHR) {
        int ci = i / (COUT*9); int r = i % (COUT*9); int co = r/9, t = r%9;
        wsm[i] = w[(co*CIN+ci)*9 + t];
    }
    __syncthreads();

    const int OHW = HOUT*WOUT;
    #pragma unroll
    for (int p = 0; p < P; p++) {
        int pos = tid + p*NTHR;
        if (pos < IMGS*OHW) {
            int im = pos / OHW, pp = pos % OHW;
            int ho = pp / WOUT, wo = pp % WOUT;
            const float* pl = planes + im*CIN*HW;
            float acc[COUT];
            #pragma unroll
            for (int co = 0; co < COUT; co++) acc[co] = 0.f;
            for (int ci = 0; ci < CIN; ci++) {
                float win[9];
                #pragma unroll
                for (int kh = 0; kh < 3; kh++)
                    #pragma unroll
                    for (int kw = 0; kw < 3; kw++) {
                        int hi = ho*2-1+kh, wi = wo*2-1+kw;
                        win[kh*3+kw] = (hi>=0 && hi<HIN && wi>=0 && wi<WIN)
                                       ? pl[ci*HW + hi*WIN + wi] : 0.f;
                    }
                const float* wp = wsm + ci*COUT*9;
                #pragma unroll
                for (int co = 0; co < COUT; co++) {
                    float s = 0.f;
                    #pragma unroll
                    for (int t = 0; t < 9; t++) s += win[t]*wp[co*9+t];
                    acc[co] += s;
                }
            }
            size_t ob = ((size_t)(blockIdx.x*IMGS + im) * COUT) * OHW + pp;
            #pragma unroll
            for (int co = 0; co < COUT; co++)
                out[ob + (size_t)co*OHW] = fmaxf(acc[co] + bias[co], 0.f);
        }
    }
}

// ---------------- deterministic BN stats ----------------
__global__ void bn_partial(const float* __restrict__ y, int HW, int nsl) {
    int c = blockIdx.x;
    long n = 512L * HW;
    long per = (n + nsl - 1) / nsl;
    long st = (long)blockIdx.y * per;
    long en = st + per; if (en > n) en = n;
    float s = 0.f, s2 = 0.f;
    for (long i = st + threadIdx.x; i < en; i += 256) {
        long b = i / HW, p = i % HW;
        float v = y[((size_t)b*24 + c)*HW + p];
        s += v; s2 += v*v;
    }
    __shared__ float sh[256], sh2[256];
    sh[threadIdx.x] = s; sh2[threadIdx.x] = s2;
    __syncthreads();
    for (int o = 128; o > 0; o >>= 1) {
        if (threadIdx.x < o) { sh[threadIdx.x] += sh[threadIdx.x+o]; sh2[threadIdx.x] += sh2[threadIdx.x+o]; }
        __syncthreads();
    }
    if (threadIdx.x == 0) { g_part1[c*16 + blockIdx.y] = sh[0]; g_part2[c*16 + blockIdx.y] = sh2[0]; }
}
__global__ void bn_finalize(const float* __restrict__ g, const float* __restrict__ beta,
                            int HW, int nsl) {
    int c = threadIdx.x;
    if (c >= 24) return;
    float s = 0.f, s2 = 0.f;
    for (int i = 0; i < nsl; i++) { s += g_part1[c*16+i]; s2 += g_part2[c*16+i]; }
    float n = 512.f * HW;
    float mean = s / n;
    float var = s2 / n - mean*mean;
    float sc = g[c] * rsqrtf(var + EPSV);
    g_scale[c] = sc;
    g_shift[c] = beta[c] - mean * sc;
}

// ---------------- layer-1 factorization ----------------
__global__ __launch_bounds__(256)
void uv_kernel(const float* __restrict__ x4, const float* __restrict__ qst,
               const float* __restrict__ gw1, const float* __restrict__ gb1,
               const float* __restrict__ scale, const float* __restrict__ shift,
               float* __restrict__ U, float* __restrict__ V) {
    extern __shared__ float us[];
    float* ws = us;            // 256*63
    float* xs = ws + 256*63;   // 600
    float* qs = xs + 600;      // 11
    const int b = blockIdx.x;
    const int k = threadIdx.x;

    for (int i = k; i < 256*63; i += 256) ws[i] = gw1[i];
    for (int i = k; i < 600; i += 256) {
        int ch = i / 25;
        xs[i] = x4[(size_t)b*600 + i] * scale[ch] + shift[ch];
    }
    if (k < 11) qs[k] = qst[b*11 + k];
    __syncthreads();

    const float* w = ws + k*63;
    float vq = gb1[k];
    #pragma unroll
    for (int q = 0; q < 11; q++) vq += qs[q] * w[52 + q];

    for (int pos = 0; pos < 25; pos++) {
        float cx = ((float)pos / 5.0f - 2.0f) * 0.5f;
        float cy = ((float)(pos % 5) - 2.0f) * 0.5f;
        float u = cx * w[24] + cy * w[25];
        float v = vq + cx * w[50] + cy * w[51];
        #pragma unroll
        for (int ch = 0; ch < 24; ch++) {
            float xv = xs[ch*25 + pos];
            u += xv * w[ch];
            v += xv * w[26 + ch];
        }
        U[(size_t)(b*25 + pos)*256 + k] = u;
        V[(size_t)(b*25 + pos)*256 + k] = v;
    }
}

// ---------------- fused g-chain: h1 -> g2 -> g3 -> g4 -> pool ----------------
// BM=128 rows/CTA (5 tiles/image), fp16 mma m16n8k16, K=256 in 4 chunks of 64.
// SMEM: S_act 4x16KB (128 rows x 64 fp16 swizzled 128B rows) + W staging 2x32KB.
__device__ __forceinline__ void issue_w(uint32_t wBase, int buf, const __half* Wp, int kc,
                                        const int* brow, const int* bj, const int* bdst) {
    #pragma unroll
    for (int it = 0; it < 8; it++)
        cp_async16(wBase + buf*32768 + bdst[it],
                   (const char*)Wp + (size_t)brow[it]*512 + kc*128 + bj[it]*16);
    cp_commit();
}

__global__ __launch_bounds__(256)
void g_fused(const float* __restrict__ U, const float* __restrict__ V,
             const __half* __restrict__ W2, const float* __restrict__ b2,
             const __half* __restrict__ W3, const float* __restrict__ b3,
             const __half* __restrict__ W4, const float* __restrict__ b4,
             float* __restrict__ Pout) {
    extern __shared__ char sm[];
    const uint32_t aBase = smem_u32(sm);
    const uint32_t wBase = aBase + 65536;
    char* wChar = sm + 65536;

    const int tid = threadIdx.x;
    const int wid = tid >> 5, lane = tid & 31;
    const int qr = lane >> 2, qc = lane & 3;
    const int wm = (wid & 1) * 64;
    const int wn = (wid >> 1) * 64;
    const int bid = blockIdx.x;
    const int b = bid / 5, tile = bid - b*5;

    // W staging geometry
    int brow[8], bj[8], bdst[8];
    #pragma unroll
    for (int it = 0; it < 8; it++) {
        int cid = it*256 + tid;
        brow[it] = cid >> 3; bj[it] = cid & 7;
        bdst[it] = brow[it]*128 + ((bj[it]*16) ^ ((brow[it] & 7) * 16));
    }

    // prefetch W2 chunks 0,1
    issue_w(wBase, 0, W2, 0, brow, bj, bdst);
    issue_w(wBase, 1, W2, 1, brow, bj, bdst);

    // ---- build h1 tile into S_act (fp16, swizzled) ----
    #pragma unroll
    for (int c = 0; c < 4; c++) {
        #pragma unroll
        for (int it = 0; it < 4; it++) {
            int idx = it*256 + tid;
            int row = idx >> 3, g = idx & 7;
            int lr = tile*128 + row;
            uint4 val = make_uint4(0u, 0u, 0u, 0u);
            if (lr < 625) {
                int a = lr / 25, cc2 = lr - a*25;
                const float* up = U + ((size_t)(b*25 + cc2))*256 + c*64 + g*8;
                const float* vp = V + ((size_t)(b*25 + a))*256 + c*64 + g*8;
                float4 u0 = *(const float4*)up;
                float4 u1 = *(const float4*)(up + 4);
                float4 v0 = *(const float4*)vp;
                float4 v1 = *(const float4*)(vp + 4);
                __half2 p0 = __floats2half2_rn(fmaxf(u0.x+v0.x,0.f), fmaxf(u0.y+v0.y,0.f));
                __half2 p1 = __floats2half2_rn(fmaxf(u0.z+v0.z,0.f), fmaxf(u0.w+v0.w,0.f));
                __half2 p2 = __floats2half2_rn(fmaxf(u1.x+v1.x,0.f), fmaxf(u1.y+v1.y,0.f));
                __half2 p3 = __floats2half2_rn(fmaxf(u1.z+v1.z,0.f), fmaxf(u1.w+v1.w,0.f));
                val.x = *reinterpret_cast<uint32_t*>(&p0);
                val.y = *reinterpret_cast<uint32_t*>(&p1);
                val.z = *reinterpret_cast<uint32_t*>(&p2);
                val.w = *reinterpret_cast<uint32_t*>(&p3);
            }
            *(uint4*)(sm + c*16384 + row*128 + ((g*16) ^ ((row & 7) * 16))) = val;
        }
    }

    float acc[4][8][4];
    #pragma unroll
    for (int mf = 0; mf < 4; mf++)
        #pragma unroll
        for (int nf = 0; nf < 8; nf++)
            #pragma unroll
            for (int i = 0; i < 4; i++) acc[mf][nf][i] = 0.f;

    const __half* Ws[3] = { W2, W3, W4 };
    const float* Bs[3] = { b2, b3, b4 };

    #pragma unroll 1
    for (int g = 0; g < 3; g++) {
        // ---- GEMM: acc = S_act @ W^T ----
        #pragma unroll
        for (int kc = 0; kc < 4; kc++) {
            if (kc < 3) cp_wait1(); else cp_wait0();
            __syncthreads();
            const char* Ab = sm + kc*16384;
            const char* Bb = wChar + (kc & 1)*32768;
            #pragma unroll
            for (int ks = 0; ks < 4; ks++) {
                const uint32_t fa = ks*32 + qc*4;
                const uint32_t o0 = fa ^ (qr*16);
                const uint32_t o1 = (fa + 16) ^ (qr*16);
                uint32_t af[4][4];
                #pragma unroll
                for (int mf = 0; mf < 4; mf++) {
                    const char* p = Ab + (wm + mf*16 + qr)*128;
                    af[mf][0] = *(const uint32_t*)(p + o0);
                    af[mf][1] = *(const uint32_t*)(p + 1024 + o0);
                    af[mf][2] = *(const uint32_t*)(p + o1);
                    af[mf][3] = *(const uint32_t*)(p + 1024 + o1);
                }
                uint32_t bf[8][2];
                #pragma unroll
                for (int nf = 0; nf < 8; nf++) {
                    const char* p = Bb + (wn + nf*8 + qr)*128;
                    bf[nf][0] = *(const uint32_t*)(p + o0);
                    bf[nf][1] = *(const uint32_t*)(p + o1);
                }
                #pragma unroll
                for (int mf = 0; mf < 4; mf++)
                    #pragma unroll
                    for (int nf = 0; nf < 8; nf++)
                        mma_f16(acc[mf][nf], af[mf], bf[nf]);
            }
            __syncthreads();
            if (kc < 2) issue_w(wBase, kc & 1, Ws[g], kc + 2, brow, bj, bdst);
        }

        if (g < 2) {
            // prefetch next weights
            issue_w(wBase, 0, Ws[g+1], 0, brow, bj, bdst);
            issue_w(wBase, 1, Ws[g+1], 1, brow, bj, bdst);
            // writeback h = relu(acc + bias) as fp16 into S_act (in place)
            const float* bp = Bs[g];
            #pragma unroll
            for (int nf = 0; nf < 8; nf++) {
                int c0 = wn + nf*8 + qc*2;
                float bb0 = bp[c0], bb1 = bp[c0+1];
                int chunk = c0 >> 6;
                int fb = (c0 & 63) * 2;            // = nf'*16 + qc*4 pattern
                int gidx = fb >> 4, rem = fb & 15;
                #pragma unroll
                for (int mf = 0; mf < 4; mf++) {
                    int r1 = wm + mf*16 + qr;
                    int r2 = r1 + 8;
                    __half2 h0 = __floats2half2_rn(fmaxf(acc[mf][nf][0]+bb0, 0.f),
                                                   fmaxf(acc[mf][nf][1]+bb1, 0.f));
                    __half2 h1 = __floats2half2_rn(fmaxf(acc[mf][nf][2]+bb0, 0.f),
                                                   fmaxf(acc[mf][nf][3]+bb1, 0.f));
                    *(__half2*)(sm + chunk*16384 + r1*128 + ((gidx*16) ^ ((r1 & 7)*16)) + rem) = h0;
                    *(__half2*)(sm + chunk*16384 + r2*128 + ((gidx*16) ^ ((r2 & 7)*16)) + rem) = h1;
                    acc[mf][nf][0] = 0.f; acc[mf][nf][1] = 0.f;
                    acc[mf][nf][2] = 0.f; acc[mf][nf][3] = 0.f;
                }
            }
            __syncthreads();
        } else {
            // ---- pooling epilogue: sum relu(acc+b4) over valid rows ----
            const int vmax = (tile < 4) ? 128 : 113;
            float* pool = (float*)wChar;   // 2 x 256 floats (W staging is free)
            const float* bp = Bs[2];
            #pragma unroll
            for (int nf = 0; nf < 8; nf++) {
                int c0 = wn + nf*8 + qc*2;
                float bb0 = bp[c0], bb1 = bp[c0+1];
                float s0 = 0.f, s1 = 0.f;
                #pragma unroll
                for (int mf = 0; mf < 4; mf++) {
                    int r1 = wm + mf*16 + qr;
                    int r2 = r1 + 8;
                    if (r1 < vmax) {
                        s0 += fmaxf(acc[mf][nf][0] + bb0, 0.f);
                        s1 += fmaxf(acc[mf][nf][1] + bb1, 0.f);
                    }
                    if (r2 < vmax) {
                        s0 += fmaxf(acc[mf][nf][2] + bb0, 0.f);
                        s1 += fmaxf(acc[mf][nf][3] + bb1, 0.f);
                    }
                }
                #pragma unroll
                for (int m = 4; m <= 16; m <<= 1) {
                    s0 += __shfl_xor_sync(0xffffffffu, s0, m);
                    s1 += __shfl_xor_sync(0xffffffffu, s1, m);
                }
                if (qr == 0) {
                    pool[(wid & 1)*256 + c0] = s0;
                    pool[(wid & 1)*256 + c0 + 1] = s1;
                }
            }
            __syncthreads();
            if (tid < 256)
                Pout[(size_t)bid*256 + tid] = pool[tid] + pool[256 + tid];
        }
    }
}

// ---------------- XG reduce (5 tiles per image) ----------------
__global__ void xg_kernel(const float* __restrict__ P, float* __restrict__ XG) {
    int b = blockIdx.x, k = threadIdx.x;
    float s = 0.f;
    #pragma unroll
    for (int t = 0; t < 5; t++) s += P[(size_t)(b*5 + t)*256 + k];
    XG[b*256 + k] = s;
}

// ---------------- SIMT GEMM for tiny f-layers ----------------
template<int RELU>
__global__ void gemm_bias_kernel(const float* __restrict__ A, const float* __restrict__ W,
                                 const float* __restrict__ bias, float* __restrict__ C,
                                 int M, int N, int K) {
    __shared__ float As[16][65];
    __shared__ float Bsm[16][65];
    const int bm = blockIdx.y * 64;
    const int bn = blockIdx.x * 64;
    const int tid = threadIdx.x;
    const int tx = tid & 15;
    const int ty = tid >> 4;
    const int lrow = tid >> 2;
    const int lcol = (tid & 3) * 4;

    float acc[4][4];
    #pragma unroll
    for (int i = 0; i < 4; i++)
        #pragma unroll
        for (int j = 0; j < 4; j++) acc[i][j] = 0.f;

    for (int k0 = 0; k0 < K; k0 += 16) {
        float4 av = make_float4(0.f,0.f,0.f,0.f);
        if (bm + lrow < M) av = *(const float4*)(A + (size_t)(bm+lrow)*K + k0 + lcol);
        As[lcol+0][lrow]=av.x; As[lcol+1][lrow]=av.y; As[lcol+2][lrow]=av.z; As[lcol+3][lrow]=av.w;
        float4 bv = make_float4(0.f,0.f,0.f,0.f);
        if (bn + lrow < N) bv = *(const float4*)(W + (size_t)(bn+lrow)*K + k0 + lcol);
        Bsm[lcol+0][lrow]=bv.x; Bsm[lcol+1][lrow]=bv.y; Bsm[lcol+2][lrow]=bv.z; Bsm[lcol+3][lrow]=bv.w;
        __syncthreads();
        #pragma unroll
        for (int kk = 0; kk < 16; kk++) {
            float a[4], bb[4];
            #pragma unroll
            for (int i = 0; i < 4; i++) a[i] = As[kk][ty*4+i];
            #pragma unroll
            for (int j = 0; j < 4; j++) bb[j] = Bsm[kk][tx*4+j];
            #pragma unroll
            for (int i = 0; i < 4; i++)
                #pragma unroll
                for (int j = 0; j < 4; j++) acc[i][j] += a[i]*bb[j];
        }
        __syncthreads();
    }
    #pragma unroll
    for (int i = 0; i < 4; i++) {
        int m = bm + ty*4 + i;
        if (m >= M) continue;
        #pragma unroll
        for (int j = 0; j < 4; j++) {
            int n = bn + tx*4 + j;
            if (n >= N) continue;
            float v = acc[i][j] + bias[n];
            if (RELU) v = fmaxf(v, 0.f);
            C[(size_t)m*N + n] = v;
        }
    }
}

// ---------------- log_softmax ----------------
__global__ void logsoftmax_kernel(const float* __restrict__ in, float* __restrict__ out) {
    int b = blockIdx.x * blockDim.x + threadIdx.x;
    if (b >= 512) return;
    float v[10];
    float m = -1e30f;
    #pragma unroll
    for (int i = 0; i < 10; i++) { v[i] = in[b*10+i]; m = fmaxf(m, v[i]); }
    float s = 0.f;
    #pragma unroll
    for (int i = 0; i < 10; i++) s += expf(v[i] - m);
    float ls = logf(s) + m;
    #pragma unroll
    for (int i = 0; i < 10; i++) out[b*10+i] = v[i] - ls;
}

// ---------------- launch ----------------
extern "C" void kernel_launch(void* const* d_in, const int* in_sizes, int n_in,
                              void* d_out, int out_size) {
    const float* img  = (const float*)d_in[0];
    const float* qst  = (const float*)d_in[1];
    const float* c1w  = (const float*)d_in[2];
    const float* c1b  = (const float*)d_in[3];
    const float* bn1g = (const float*)d_in[4];
    const float* bn1b = (const float*)d_in[5];
    const float* c2w  = (const float*)d_in[6];
    const float* c2b  = (const float*)d_in[7];
    const float* bn2g = (const float*)d_in[8];
    const float* bn2b = (const float*)d_in[9];
    const float* c3w  = (const float*)d_in[10];
    const float* c3b  = (const float*)d_in[11];
    const float* bn3g = (const float*)d_in[12];
    const float* bn3b = (const float*)d_in[13];
    const float* c4w  = (const float*)d_in[14];
    const float* c4b  = (const float*)d_in[15];
    const float* bn4g = (const float*)d_in[16];
    const float* bn4b = (const float*)d_in[17];
    const float* gw1  = (const float*)d_in[18];
    const float* gb1  = (const float*)d_in[19];
    const float* gw2  = (const float*)d_in[20];
    const float* gb2  = (const float*)d_in[21];
    const float* gw3  = (const float*)d_in[22];
    const float* gb3  = (const float*)d_in[23];
    const float* gw4  = (const float*)d_in[24];
    const float* gb4  = (const float*)d_in[25];
    const float* fw1  = (const float*)d_in[26];
    const float* fb1  = (const float*)d_in[27];
    const float* fw2  = (const float*)d_in[28];
    const float* fb2  = (const float*)d_in[29];
    const float* fw3  = (const float*)d_in[30];
    const float* fb3  = (const float*)d_in[31];
    float* out = (float*)d_out;

    float *buf1,*buf2,*buf3,*buf4,*scale,*shift,*U,*V,*P,*XG,*F1,*F2,*FO;
    __half *W2h,*W3h,*W4h;
    cudaGetSymbolAddress((void**)&buf1, g_buf1);
    cudaGetSymbolAddress((void**)&buf2, g_buf2);
    cudaGetSymbolAddress((void**)&buf3, g_buf3);
    cudaGetSymbolAddress((void**)&buf4, g_buf4);
    cudaGetSymbolAddress((void**)&scale, g_scale);
    cudaGetSymbolAddress((void**)&shift, g_shift);
    cudaGetSymbolAddress((void**)&U, g_U);
    cudaGetSymbolAddress((void**)&V, g_V);
    cudaGetSymbolAddress((void**)&P, g_P);
    cudaGetSymbolAddress((void**)&XG, g_XG);
    cudaGetSymbolAddress((void**)&F1, g_F1);
    cudaGetSymbolAddress((void**)&F2, g_F2);
    cudaGetSymbolAddress((void**)&FO, g_FO);
    cudaGetSymbolAddress((void**)&W2h, g_W2h);
    cudaGetSymbolAddress((void**)&W3h, g_W3h);
    cudaGetSymbolAddress((void**)&W4h, g_W4h);

    // smem sizes
    const int C1_SMEM = (1*3*75*75 + 3*24*9) * 4;        // 70092
    const int C2_SMEM = (1*24*38*38 + 24*24*9) * 4;      // 159360
    const int C3_SMEM = (2*24*19*19 + 24*24*9) * 4;      // 90048
    const int C4_SMEM = (8*24*10*10 + 24*24*9) * 4;      // 97536
    const int UV_SMEM = (256*63 + 600 + 16) * 4;
    const int GF_SMEM = 65536 + 65536;                   // 131072

    cudaFuncSetAttribute((const void*)conv_res_kernel<3,24,75,75,38,38,768,2,0,1>,
                         cudaFuncAttributeMaxDynamicSharedMemorySize, C1_SMEM);
    cudaFuncSetAttribute((const void*)conv_res_kernel<24,24,38,38,19,19,384,1,1,1>,
                         cudaFuncAttributeMaxDynamicSharedMemorySize, C2_SMEM);
    cudaFuncSetAttribute((const void*)conv_res_kernel<24,24,19,19,10,10,256,1,1,2>,
                         cudaFuncAttributeMaxDynamicSharedMemorySize, C3_SMEM);
    cudaFuncSetAttribute((const void*)conv_res_kernel<24,24,10,10,5,5,256,1,1,8>,
                         cudaFuncAttributeMaxDynamicSharedMemorySize, C4_SMEM);
    cudaFuncSetAttribute((const void*)uv_kernel,
                         cudaFuncAttributeMaxDynamicSharedMemorySize, UV_SMEM);
    cudaFuncSetAttribute((const void*)g_fused,
                         cudaFuncAttributeMaxDynamicSharedMemorySize, GF_SMEM);

    // weights -> fp16 (each launch; deterministic)
    w_to_half<<<256, 256>>>(gw2, W2h, 65536);
    w_to_half<<<256, 256>>>(gw3, W3h, 65536);
    w_to_half<<<256, 256>>>(gw4, W4h, 65536);

    // conv stack (+ deterministic BN)
    conv_res_kernel<3,24,75,75,38,38,768,2,0,1><<<512,768,C1_SMEM>>>(img, c1w, c1b, scale, shift, buf1);
    bn_partial<<<dim3(24,16),256>>>(buf1, 38*38, 16);
    bn_finalize<<<1,32>>>(bn1g, bn1b, 38*38, 16);

    conv_res_kernel<24,24,38,38,19,19,384,1,1,1><<<512,384,C2_SMEM>>>(buf1, c2w, c2b, scale, shift, buf2);
    bn_partial<<<dim3(24,8),256>>>(buf2, 19*19, 8);
    bn_finalize<<<1,32>>>(bn2g, bn2b, 19*19, 8);

    conv_res_kernel<24,24,19,19,10,10,256,1,1,2><<<256,256,C3_SMEM>>>(buf2, c3w, c3b, scale, shift, buf3);
    bn_partial<<<dim3(24,4),256>>>(buf3, 10*10, 4);
    bn_finalize<<<1,32>>>(bn3g, bn3b, 10*10, 4);

    conv_res_kernel<24,24,10,10,5,5,256,1,1,8><<<64,256,C4_SMEM>>>(buf3, c4w, c4b, scale, shift, buf4);
    bn_partial<<<dim3(24,2),256>>>(buf4, 5*5, 2);
    bn_finalize<<<1,32>>>(bn4g, bn4b, 5*5, 2);

    // g layer 1 factorized (bn4 folded in)
    uv_kernel<<<512, 256, UV_SMEM>>>(buf4, qst, gw1, gb1, scale, shift, U, V);

    // fused g2-g4 + pooling
    g_fused<<<2560, 256, GF_SMEM>>>(U, V, W2h, gb2, W3h, gb3, W4h, gb4, P);
    xg_kernel<<<512, 256>>>(P, XG);

    // f layers (tiny)
    {
        dim3 grid(4, 8), block(256);
        gemm_bias_kernel<1><<<grid, block>>>(XG, fw1, fb1, F1, 512, 256, 256);
        gemm_bias_kernel<1><<<grid, block>>>(F1, fw2, fb2, F2, 512, 256, 256);
        dim3 grid3(1, 8);
        gemm_bias_kernel<0><<<grid3, block>>>(F2, fw3, fb3, FO, 512, 10, 256);
    }

    logsoftmax_kernel<<<2, 256>>>(FO, out);
}